// round 6
// baseline (speedup 1.0000x reference)
#include <cuda_runtime.h>

// CAN co-action unit: per-sample 2-layer MLP, D=16, N=50, B=16384.
// R3 memory structure (direct strided LDG/STG, x in regs, weights via
// broadcast LDS from padded smem, 2 same-sample rows/thread) with:
//  - packed f32x2 FFMA2 compute (~27% fewer issue-path instructions)
//  - sample-decoupled row-pair mapping: 256 pairs/CTA, zero idle threads
//  - launch_bounds(256,3): 24 warps/SM

#define D 16
#define N 50
#define PARAMS 544            // 2*(256+16)
#define PSTRIDE 552           // padded param stride, words (%32==8 -> bank shift)
#define THREADS 256
#define SPC_MAX 12            // samples a CTA's 256 pairs can touch
#define PWORDS (SPC_MAX * PSTRIDE)

__device__ __forceinline__ unsigned long long splat2(float x) {
    unsigned long long r; unsigned u = __float_as_uint(x);
    asm("mov.b64 %0, {%1, %1};" : "=l"(r) : "r"(u));
    return r;
}
__device__ __forceinline__ void ffma2(unsigned long long& d,
                                      unsigned long long a, unsigned long long b) {
    asm("fma.rn.f32x2 %0, %1, %2, %0;" : "+l"(d) : "l"(a), "l"(b));
}
__device__ __forceinline__ void unpack2(unsigned long long v, float& lo, float& hi) {
    unsigned a, b;
    asm("mov.b64 {%0, %1}, %2;" : "=r"(a), "=r"(b) : "l"(v));
    lo = __uint_as_float(a); hi = __uint_as_float(b);
}

__global__ __launch_bounds__(THREADS, 3) void can_kernel(
    const float* __restrict__ user_emb,
    const float* __restrict__ item_emb,
    float* __restrict__ out,
    int B)
{
    __shared__ float sp[PWORDS];

    const int t = threadIdx.x;
    const int base_pair = blockIdx.x * THREADS;
    const int base_s = base_pair / 25;          // first sample this CTA touches

    // ---- Stage params for up to 12 samples (136 float4 each), coalesced.
    for (int i = t; i < SPC_MAX * (PARAMS / 4); i += THREADS) {
        int si = i / (PARAMS / 4);
        int wi = i - si * (PARAMS / 4);
        int gs = base_s + si;
        if (gs >= B) gs = B - 1;                // clamp (duplicate, harmless)
        *(float4*)(sp + si * PSTRIDE + wi * 4) =
            ((const float4*)(item_emb + (size_t)gs * PARAMS))[wi];
    }

    // ---- This thread's row pair (always same sample).
    const int P = base_pair + t;
    const int s = P / 25;
    const int j = P - s * 25;
    const float* p = sp + (s - base_s) * PSTRIDE;
    const size_t row0 = (size_t)s * N + j;      // global rows: row0, row0+25

    // x rows straight into registers (4x LDG.128 each).
    float x0[D], x1[D];
    {
        const float4* r0 = (const float4*)(user_emb + row0 * D);
        const float4* r1 = (const float4*)(user_emb + (row0 + 25) * D);
        #pragma unroll
        for (int q = 0; q < 4; q++) {
            float4 a = r0[q], b = r1[q];
            x0[4*q+0]=a.x; x0[4*q+1]=a.y; x0[4*q+2]=a.z; x0[4*q+3]=a.w;
            x1[4*q+0]=b.x; x1[4*q+1]=b.y; x1[4*q+2]=b.z; x1[4*q+3]=b.w;
        }
    }
    __syncthreads();

    unsigned long long a0[8], a1[8];

    // ---- Layer 1: relu(x W0 + b0).  W0 = p[0..255], b0 = p[256..271].
    {
        const ulonglong2* bp = (const ulonglong2*)(p + 256);
        #pragma unroll
        for (int h = 0; h < 4; h++) {
            ulonglong2 bv = bp[h];
            a0[2*h]=bv.x; a0[2*h+1]=bv.y;
            a1[2*h]=bv.x; a1[2*h+1]=bv.y;
        }
        #pragma unroll
        for (int d = 0; d < D; d++) {
            const ulonglong2* wr = (const ulonglong2*)(p + d * D);
            ulonglong2 wA = wr[0], wB = wr[1], wC = wr[2], wE = wr[3];
            unsigned long long u0 = splat2(x0[d]), u1 = splat2(x1[d]);
            ffma2(a0[0],u0,wA.x); ffma2(a1[0],u1,wA.x);
            ffma2(a0[1],u0,wA.y); ffma2(a1[1],u1,wA.y);
            ffma2(a0[2],u0,wB.x); ffma2(a1[2],u1,wB.x);
            ffma2(a0[3],u0,wB.y); ffma2(a1[3],u1,wB.y);
            ffma2(a0[4],u0,wC.x); ffma2(a1[4],u1,wC.x);
            ffma2(a0[5],u0,wC.y); ffma2(a1[5],u1,wC.y);
            ffma2(a0[6],u0,wE.x); ffma2(a1[6],u1,wE.x);
            ffma2(a0[7],u0,wE.y); ffma2(a1[7],u1,wE.y);
        }
        #pragma unroll
        for (int h = 0; h < 8; h++) {
            float lo, hi;
            unpack2(a0[h], lo, hi);
            x0[2*h] = fmaxf(lo, 0.0f); x0[2*h+1] = fmaxf(hi, 0.0f);
            unpack2(a1[h], lo, hi);
            x1[2*h] = fmaxf(lo, 0.0f); x1[2*h+1] = fmaxf(hi, 0.0f);
        }
    }

    // ---- Layer 2: x W1 + b1.  W1 = p[272..527], b1 = p[528..543].
    {
        const ulonglong2* bp = (const ulonglong2*)(p + 528);
        #pragma unroll
        for (int h = 0; h < 4; h++) {
            ulonglong2 bv = bp[h];
            a0[2*h]=bv.x; a0[2*h+1]=bv.y;
            a1[2*h]=bv.x; a1[2*h+1]=bv.y;
        }
        #pragma unroll
        for (int d = 0; d < D; d++) {
            const ulonglong2* wr = (const ulonglong2*)(p + 272 + d * D);
            ulonglong2 wA = wr[0], wB = wr[1], wC = wr[2], wE = wr[3];
            unsigned long long u0 = splat2(x0[d]), u1 = splat2(x1[d]);
            ffma2(a0[0],u0,wA.x); ffma2(a1[0],u1,wA.x);
            ffma2(a0[1],u0,wA.y); ffma2(a1[1],u1,wA.y);
            ffma2(a0[2],u0,wB.x); ffma2(a1[2],u1,wB.x);
            ffma2(a0[3],u0,wB.y); ffma2(a1[3],u1,wB.y);
            ffma2(a0[4],u0,wC.x); ffma2(a1[4],u1,wC.x);
            ffma2(a0[5],u0,wC.y); ffma2(a1[5],u1,wC.y);
            ffma2(a0[6],u0,wE.x); ffma2(a1[6],u1,wE.x);
            ffma2(a0[7],u0,wE.y); ffma2(a1[7],u1,wE.y);
        }
    }

    // ---- Relu + store both rows (4x STG.128 each).
    {
        float4* o0 = (float4*)(out + row0 * D);
        float4* o1 = (float4*)(out + (row0 + 25) * D);
        #pragma unroll
        for (int q = 0; q < 4; q++) {
            float l0,h0,l1,h1, l2,h2,l3,h3;
            unpack2(a0[2*q],   l0, h0); unpack2(a0[2*q+1], l1, h1);
            unpack2(a1[2*q],   l2, h2); unpack2(a1[2*q+1], l3, h3);
            float4 v0 = { fmaxf(l0,0.f), fmaxf(h0,0.f), fmaxf(l1,0.f), fmaxf(h1,0.f) };
            float4 v1 = { fmaxf(l2,0.f), fmaxf(h2,0.f), fmaxf(l3,0.f), fmaxf(h3,0.f) };
            o0[q] = v0;
            o1[q] = v1;
        }
    }
}

extern "C" void kernel_launch(void* const* d_in, const int* in_sizes, int n_in,
                              void* d_out, int out_size) {
    const float* user_emb = (const float*)d_in[0];
    const float* item_emb = (const float*)d_in[1];
    float* out = (float*)d_out;
    const int B = in_sizes[1] / PARAMS;           // 16384
    const int pairs = B * (N / 2);                // 409600
    can_kernel<<<pairs / THREADS, THREADS>>>(user_emb, item_emb, out, B);
}

// round 7
// speedup vs baseline: 1.1355x; 1.1355x over previous
#include <cuda_runtime.h>
#include <cstdint>

// CAN co-action unit: per-sample 2-layer MLP, D=16, N=50, B=16384.
// R3 compute core (scalar fmaf, 2 same-sample rows/thread, weights via
// broadcast LDS.128 from 552-word-padded smem) with all global traffic moved
// to cp.async.bulk (UBLKCP): bulk-load x tile + per-sample params, compute
// out-of/into smem with chunk-rotated LDS/STS (4-wf data floor), bulk-store
// the dense output tile. Removes the 16x LDG/STG wavefront amplification.

#define D 16
#define N 50
#define PARAMS 544            // 2*(256+16)
#define PSTRIDE 552           // padded param stride, words (%32==8 -> bank shift)
#define SPC 8                 // samples per CTA
#define TPS 25                // threads per sample (2 rows each)
#define THREADS 224
#define ACTIVE (SPC * TPS)    // 200
#define CTA_ROWS (SPC * N)    // 400
#define PWORDS (SPC * PSTRIDE)   // 4416
#define XWORDS (CTA_ROWS * D)    // 6400
#define X_BYTES (CTA_ROWS * D * 4)        // 25600
#define P_BYTES (PARAMS * 4)              // 2176 per sample
#define TX_TOTAL (X_BYTES + SPC * P_BYTES)

__device__ __forceinline__ uint32_t s2u(const void* p) {
    uint32_t a;
    asm("{ .reg .u64 t; cvta.to.shared.u64 t, %1; cvt.u32.u64 %0, t; }"
        : "=r"(a) : "l"(p));
    return a;
}

__global__ __launch_bounds__(THREADS, 3) void can_kernel(
    const float* __restrict__ user_emb,
    const float* __restrict__ item_emb,
    float* __restrict__ out)
{
    __shared__ float sp[PWORDS];               // params, padded
    __shared__ float sx[XWORDS];               // x tile (dense), reused for out
    __shared__ alignas(8) uint64_t mbar;

    const int t = threadIdx.x;
    const uint32_t mb = s2u(&mbar);

    if (t == 0) {
        asm volatile("mbarrier.init.shared.b64 [%0], 1;" :: "r"(mb) : "memory");
        asm volatile("fence.proxy.async.shared::cta;" ::: "memory");
    }
    __syncthreads();

    if (t == 0) {
        asm volatile("mbarrier.arrive.expect_tx.shared.b64 _, [%0], %1;"
                     :: "r"(mb), "r"((uint32_t)TX_TOTAL) : "memory");
        // x tile: one contiguous bulk copy.
        asm volatile("cp.async.bulk.shared::cta.global.mbarrier::complete_tx::bytes"
                     " [%0], [%1], %2, [%3];"
                     :: "r"(s2u(sx)),
                        "l"(user_emb + (size_t)blockIdx.x * CTA_ROWS * D),
                        "r"((uint32_t)X_BYTES), "r"(mb) : "memory");
        // params: one bulk copy per sample into padded base.
        #pragma unroll
        for (int s = 0; s < SPC; s++) {
            asm volatile("cp.async.bulk.shared::cta.global.mbarrier::complete_tx::bytes"
                         " [%0], [%1], %2, [%3];"
                         :: "r"(s2u(sp + s * PSTRIDE)),
                            "l"(item_emb + ((size_t)blockIdx.x * SPC + s) * PARAMS),
                            "r"((uint32_t)P_BYTES), "r"(mb) : "memory");
        }
    }

    // All threads wait for the bulk loads.
    {
        uint32_t done;
        asm volatile(
            "{\n\t.reg .pred p;\n\t"
            "mbarrier.try_wait.parity.acquire.cta.shared::cta.b64 p, [%1], 0;\n\t"
            "selp.b32 %0, 1, 0, p;\n\t}"
            : "=r"(done) : "r"(mb) : "memory");
        while (!done) {
            asm volatile(
                "{\n\t.reg .pred p;\n\t"
                "mbarrier.try_wait.parity.acquire.cta.shared::cta.b64 p, [%1], 0, 0x989680;\n\t"
                "selp.b32 %0, 1, 0, p;\n\t}"
                : "=r"(done) : "r"(mb) : "memory");
        }
    }

    if (t < ACTIVE) {
        const int s = t / TPS;
        const int j = t - s * TPS;
        const float* p = sp + s * PSTRIDE;
        const int r0 = s * N + j;       // local rows: r0 and r0+25 (same sample)
        const int r1 = r0 + TPS;

        // x rows -> registers. Chunk-rotated LDS.128 (4-wf data floor).
        float x0[D], x1[D];
        #pragma unroll
        for (int q = 0; q < 4; q++) {
            const int c0 = (q + (r0 >> 1)) & 3;
            const int c1 = (q + (r1 >> 1)) & 3;
            float4 a = *(const float4*)(sx + r0 * D + c0 * 4);
            float4 b = *(const float4*)(sx + r1 * D + c1 * 4);
            x0[4*c0+0]=a.x; x0[4*c0+1]=a.y; x0[4*c0+2]=a.z; x0[4*c0+3]=a.w;
            x1[4*c1+0]=b.x; x1[4*c1+1]=b.y; x1[4*c1+2]=b.z; x1[4*c1+3]=b.w;
        }

        float a0[D], a1[D];

        // ---- Layer 1: relu(x W0 + b0). W0=p[0..255], b0=p[256..271].
        {
            const float4* bias = (const float4*)(p + 256);
            #pragma unroll
            for (int q = 0; q < 4; q++) {
                float4 v = bias[q];
                a0[4*q+0]=v.x; a0[4*q+1]=v.y; a0[4*q+2]=v.z; a0[4*q+3]=v.w;
                a1[4*q+0]=v.x; a1[4*q+1]=v.y; a1[4*q+2]=v.z; a1[4*q+3]=v.w;
            }
            #pragma unroll
            for (int d = 0; d < D; d++) {
                const float4* wr = (const float4*)(p + d * D);
                const float u0 = x0[d], u1 = x1[d];
                #pragma unroll
                for (int q = 0; q < 4; q++) {
                    float4 w = wr[q];
                    a0[4*q+0]=fmaf(u0,w.x,a0[4*q+0]); a1[4*q+0]=fmaf(u1,w.x,a1[4*q+0]);
                    a0[4*q+1]=fmaf(u0,w.y,a0[4*q+1]); a1[4*q+1]=fmaf(u1,w.y,a1[4*q+1]);
                    a0[4*q+2]=fmaf(u0,w.z,a0[4*q+2]); a1[4*q+2]=fmaf(u1,w.z,a1[4*q+2]);
                    a0[4*q+3]=fmaf(u0,w.w,a0[4*q+3]); a1[4*q+3]=fmaf(u1,w.w,a1[4*q+3]);
                }
            }
            #pragma unroll
            for (int e = 0; e < D; e++) {
                x0[e] = fmaxf(a0[e], 0.0f);
                x1[e] = fmaxf(a1[e], 0.0f);
            }
        }

        // ---- Layer 2: x W1 + b1. W1=p[272..527], b1=p[528..543].
        {
            const float4* bias = (const float4*)(p + 528);
            #pragma unroll
            for (int q = 0; q < 4; q++) {
                float4 v = bias[q];
                a0[4*q+0]=v.x; a0[4*q+1]=v.y; a0[4*q+2]=v.z; a0[4*q+3]=v.w;
                a1[4*q+0]=v.x; a1[4*q+1]=v.y; a1[4*q+2]=v.z; a1[4*q+3]=v.w;
            }
            #pragma unroll
            for (int d = 0; d < D; d++) {
                const float4* wr = (const float4*)(p + 272 + d * D);
                const float u0 = x0[d], u1 = x1[d];
                #pragma unroll
                for (int q = 0; q < 4; q++) {
                    float4 w = wr[q];
                    a0[4*q+0]=fmaf(u0,w.x,a0[4*q+0]); a1[4*q+0]=fmaf(u1,w.x,a1[4*q+0]);
                    a0[4*q+1]=fmaf(u0,w.y,a0[4*q+1]); a1[4*q+1]=fmaf(u1,w.y,a1[4*q+1]);
                    a0[4*q+2]=fmaf(u0,w.z,a0[4*q+2]); a1[4*q+2]=fmaf(u1,w.z,a1[4*q+2]);
                    a0[4*q+3]=fmaf(u0,w.w,a0[4*q+3]); a1[4*q+3]=fmaf(u1,w.w,a1[4*q+3]);
                }
            }
        }

        // ---- Relu + write back into own x slots (no cross-thread hazard),
        // chunk-rotated STS.128.
        #pragma unroll
        for (int q = 0; q < 4; q++) {
            const int c0 = (q + (r0 >> 1)) & 3;
            const int c1 = (q + (r1 >> 1)) & 3;
            float4 v0 = { fmaxf(a0[4*c0+0],0.f), fmaxf(a0[4*c0+1],0.f),
                          fmaxf(a0[4*c0+2],0.f), fmaxf(a0[4*c0+3],0.f) };
            float4 v1 = { fmaxf(a1[4*c1+0],0.f), fmaxf(a1[4*c1+1],0.f),
                          fmaxf(a1[4*c1+2],0.f), fmaxf(a1[4*c1+3],0.f) };
            *(float4*)(sx + r0 * D + c0 * 4) = v0;
            *(float4*)(sx + r1 * D + c1 * 4) = v1;
        }
    }
    __syncthreads();

    // ---- Bulk store of the dense output tile.
    if (t == 0) {
        asm volatile("fence.proxy.async.shared::cta;" ::: "memory");
        asm volatile("cp.async.bulk.global.shared::cta.bulk_group [%0], [%1], %2;"
                     :: "l"(out + (size_t)blockIdx.x * CTA_ROWS * D),
                        "r"(s2u(sx)), "r"((uint32_t)X_BYTES) : "memory");
        asm volatile("cp.async.bulk.commit_group;" ::: "memory");
        asm volatile("cp.async.bulk.wait_group 0;" ::: "memory");
    }
}

extern "C" void kernel_launch(void* const* d_in, const int* in_sizes, int n_in,
                              void* d_out, int out_size) {
    const float* user_emb = (const float*)d_in[0];
    const float* item_emb = (const float*)d_in[1];
    float* out = (float*)d_out;
    const int B = in_sizes[1] / PARAMS;   // 16384
    can_kernel<<<B / SPC, THREADS>>>(user_emb, item_emb, out);
}